// round 9
// baseline (speedup 1.0000x reference)
#include <cuda_runtime.h>
#include <cstdint>

// LSHGaussian, fully tensorized:
//   scores  T = A_feat @ B_feat^T  via 3x-tf32 m16n8k8 (split hi/lo features,
//            fp32-accurate), A_feat per-warp constant in registers;
//   weights w = ex2(T) packed f16x2 -> A fragments of the U-GEMM;
//   U-GEMM  via fp16 m16n8k16 (same 10-bit mantissa as tf32).
//   grid=128 CTAs x 512 threads (16 warps = 8 row-blocks x 2 j-halves),
//   double-buffered U + feature tiles, one syncthreads per tile.
// out = P @ U - U,  P[i,j] = exp(-0.5*||ref_i-ref_j||^2).

#define N_PTS  16384
#define CCH    64
#define BM     128
#define BK     128
#define TPB    512
#define NTILES (N_PTS / BK)
#define USTR2  72          // u32 stride per jp row of U tile (conflict-free)

#define US_BYTES (64 * USTR2 * 4)      // 18432 per buffer
#define FT_BYTES (BK * 8 * 4)          // 4096 per feature buffer
#define OFF_US0  0
#define OFF_US1  US_BYTES
#define OFF_FH0  (2 * US_BYTES)                 // 36864
#define OFF_FH1  (OFF_FH0 + FT_BYTES)
#define OFF_FL0  (OFF_FH0 + 2 * FT_BYTES)
#define OFF_FL1  (OFF_FH0 + 3 * FT_BYTES)
#define SMEM_TOTAL (OFF_FH0 + 4 * FT_BYTES)     // 53248

__device__ __forceinline__ float ex2f(float x) {
    float r; asm("ex2.approx.ftz.f32 %0, %1;" : "=f"(r) : "f"(x)); return r;
}
__device__ __forceinline__ float tf32f(float x) {       // round-to-tf32, as float
    uint32_t r; asm("cvt.rna.tf32.f32 %0, %1;" : "=r"(r) : "f"(x));
    return __uint_as_float(r);
}
#define CVTH(d, hi, lo) asm("cvt.rn.f16x2.f32 %0, %1, %2;" : "=r"(d) : "f"(hi), "f"(lo))
#define MMA_S(cc, a0, a1, a2, a3, b0, b1) \
    asm volatile("mma.sync.aligned.m16n8k8.row.col.f32.tf32.tf32.f32 " \
                 "{%0,%1,%2,%3}, {%4,%5,%6,%7}, {%8,%9}, {%0,%1,%2,%3};" \
                 : "+f"((cc)[0]), "+f"((cc)[1]), "+f"((cc)[2]), "+f"((cc)[3]) \
                 : "r"(a0), "r"(a1), "r"(a2), "r"(a3), "r"(b0), "r"(b1))
#define MMA16(cc, a0, a1, a2, a3, b0, b1) \
    asm volatile("mma.sync.aligned.m16n8k16.row.col.f32.f16.f16.f32 " \
                 "{%0,%1,%2,%3}, {%4,%5,%6,%7}, {%8,%9}, {%0,%1,%2,%3};" \
                 : "+f"((cc)[0]), "+f"((cc)[1]), "+f"((cc)[2]), "+f"((cc)[3]) \
                 : "r"(a0), "r"(a1), "r"(a2), "r"(a3), "r"(b0), "r"(b1))

__global__ void __launch_bounds__(TPB, 1)
lsh_tmma_kernel(const float* __restrict__ U, const float* __restrict__ ref,
                float* __restrict__ out)
{
    extern __shared__ __align__(16) char smem[];
    uint32_t* const UsB[2] = { (uint32_t*)(smem + OFF_US0), (uint32_t*)(smem + OFF_US1) };
    float*    const FhB[2] = { (float*)(smem + OFF_FH0), (float*)(smem + OFF_FH1) };
    float*    const FlB[2] = { (float*)(smem + OFF_FL0), (float*)(smem + OFF_FL1) };

    const int tid  = threadIdx.x;
    const int wid  = tid >> 5;
    const int lane = tid & 31;
    const int g    = lane >> 2;        // 0..7
    const int kin  = lane & 3;         // 0..3
    const int h    = wid >> 3;         // j-half (0/1)
    const int wm   = wid & 7;          // row-block (16 rows)
    const float L2E = 1.4426950408889634f;
    const int rbase = blockIdx.x * BM + wm * 16;

    // ── per-warp-constant A features (3x-tf32 split), rows g and g+8 ──
    // A[i] = [L2E*ri0..4, bi, 1, 0]; this thread needs k = kin and kin+4.
    uint32_t ahi[4], alo[4];
    {
        float vl[8], vh[8];
        const float* rl = ref + (size_t)(rbase + g) * 5;
        const float* rh = ref + (size_t)(rbase + 8 + g) * 5;
        float sl = 0.f, sh = 0.f;
        #pragma unroll
        for (int k = 0; k < 5; ++k) {
            float a = rl[k], b = rh[k];
            sl = fmaf(a, a, sl); sh = fmaf(b, b, sh);
            vl[k] = a * L2E; vh[k] = b * L2E;
        }
        vl[5] = -0.5f * L2E * sl; vh[5] = -0.5f * L2E * sh;
        vl[6] = 1.f; vh[6] = 1.f; vl[7] = 0.f; vh[7] = 0.f;
        float xs[4] = { vl[kin], vh[kin], vl[kin + 4], vh[kin + 4] };
        #pragma unroll
        for (int q = 0; q < 4; ++q) {
            float hi = tf32f(xs[q]);
            ahi[q] = __float_as_uint(hi);
            alo[q] = __float_as_uint(tf32f(xs[q] - hi));
        }
    }

    float c[8][4];
    #pragma unroll
    for (int nt = 0; nt < 8; ++nt)
        #pragma unroll
        for (int q = 0; q < 4; ++q) c[nt][q] = 0.f;

    // ── stage tile 0 ──
    {
        const float4* Ug = (const float4*)U;
        #pragma unroll
        for (int it = 0; it < 2; ++it) {
            int f = it * TPB + tid, jp = f >> 4, c4 = f & 15;
            float4 vA = Ug[(2 * jp) * 16 + c4];
            float4 vB = Ug[(2 * jp + 1) * 16 + c4];
            uint4 w;
            CVTH(w.x, vB.x, vA.x); CVTH(w.y, vB.y, vA.y);
            CVTH(w.z, vB.z, vA.z); CVTH(w.w, vB.w, vA.w);
            *(uint4*)&UsB[0][jp * USTR2 + c4 * 4] = w;
        }
        if (tid < BK) {
            const float* rj = ref + (size_t)tid * 5;
            float v[8]; float s = 0.f;
            #pragma unroll
            for (int k = 0; k < 5; ++k) { v[k] = rj[k]; s = fmaf(v[k], v[k], s); }
            v[5] = 1.f; v[6] = -0.5f * L2E * s; v[7] = 0.f;
            float* FH = FhB[0] + tid * 8;
            float* FL = FlB[0] + tid * 8;
            #pragma unroll
            for (int k = 0; k < 8; ++k) {
                float hi = tf32f(v[k]);
                FH[k] = hi;
                FL[k] = tf32f(v[k] - hi);
            }
        }
    }
    __syncthreads();

    for (int t = 0; t < NTILES; ++t) {
        const int buf = t & 1, nbuf = buf ^ 1;
        const bool pfv = (t + 1 < NTILES);

        // prefetch next tile into registers
        float4 pA[2], pB[2]; float pa[5];
        if (pfv) {
            const float4* Ug = (const float4*)(U + (size_t)(t + 1) * BK * CCH);
            #pragma unroll
            for (int it = 0; it < 2; ++it) {
                int f = it * TPB + tid, jp = f >> 4, c4 = f & 15;
                pA[it] = Ug[(2 * jp) * 16 + c4];
                pB[it] = Ug[(2 * jp + 1) * 16 + c4];
            }
            if (tid < BK) {
                const float* rj = ref + (size_t)((t + 1) * BK + tid) * 5;
                #pragma unroll
                for (int k = 0; k < 5; ++k) pa[k] = rj[k];
            }
        }

        // ── compute tile t ──
        {
            const uint32_t* __restrict__ Ub = UsB[buf];
            const float*    __restrict__ FH = FhB[buf];
            const float*    __restrict__ FL = FlB[buf];
            #pragma unroll
            for (int kc = 0; kc < 4; ++kc) {
                // scores for the two 8-j groups of this 16-j chunk (3x tf32)
                float s0[4] = {0.f, 0.f, 0.f, 0.f};
                float s1[4] = {0.f, 0.f, 0.f, 0.f};
                const int jn0 = (h * 64 + kc * 16 + g) * 8;
                const int jn1 = jn0 + 64;               // +8 j rows
                uint32_t bh0 = __float_as_uint(FH[jn0 + kin]);
                uint32_t bh1 = __float_as_uint(FH[jn0 + kin + 4]);
                uint32_t bl0 = __float_as_uint(FL[jn0 + kin]);
                uint32_t bl1 = __float_as_uint(FL[jn0 + kin + 4]);
                uint32_t dh0 = __float_as_uint(FH[jn1 + kin]);
                uint32_t dh1 = __float_as_uint(FH[jn1 + kin + 4]);
                uint32_t dl0 = __float_as_uint(FL[jn1 + kin]);
                uint32_t dl1 = __float_as_uint(FL[jn1 + kin + 4]);
                MMA_S(s0, ahi[0], ahi[1], ahi[2], ahi[3], bh0, bh1);
                MMA_S(s1, ahi[0], ahi[1], ahi[2], ahi[3], dh0, dh1);
                MMA_S(s0, ahi[0], ahi[1], ahi[2], ahi[3], bl0, bl1);
                MMA_S(s1, ahi[0], ahi[1], ahi[2], ahi[3], dl0, dl1);
                MMA_S(s0, alo[0], alo[1], alo[2], alo[3], bh0, bh1);
                MMA_S(s1, alo[0], alo[1], alo[2], alo[3], dh0, dh1);

                // weights: ex2 + pack into fp16 A fragments
                uint32_t a0, a1, a2, a3;
                CVTH(a0, ex2f(s0[1]), ex2f(s0[0]));     // (g,   2kin..+1)
                CVTH(a1, ex2f(s0[3]), ex2f(s0[2]));     // (g+8, 2kin..+1)
                CVTH(a2, ex2f(s1[1]), ex2f(s1[0]));     // (g,   2kin+8..)
                CVTH(a3, ex2f(s1[3]), ex2f(s1[2]));     // (g+8, 2kin+8..)

                // U-GEMM for this 16-j chunk
                const int jpA = h * 32 + kc * 8 + kin;
                const uint32_t* u0 = &Ub[jpA * USTR2 + g];
                const uint32_t* u1 = &Ub[(jpA + 4) * USTR2 + g];
                #pragma unroll
                for (int nt = 0; nt < 8; ++nt) {
                    uint32_t b0 = u0[nt * 8];
                    uint32_t b1 = u1[nt * 8];
                    MMA16(c[nt], a0, a1, a2, a3, b0, b1);
                }
            }
        }

        // ── stage tile t+1 ──
        if (pfv) {
            uint32_t* Ud = UsB[nbuf];
            #pragma unroll
            for (int it = 0; it < 2; ++it) {
                int f = it * TPB + tid, jp = f >> 4, c4 = f & 15;
                uint4 w;
                CVTH(w.x, pB[it].x, pA[it].x); CVTH(w.y, pB[it].y, pA[it].y);
                CVTH(w.z, pB[it].z, pA[it].z); CVTH(w.w, pB[it].w, pA[it].w);
                *(uint4*)&Ud[jp * USTR2 + c4 * 4] = w;
            }
            if (tid < BK) {
                float v[8]; float s = 0.f;
                #pragma unroll
                for (int k = 0; k < 5; ++k) { v[k] = pa[k]; s = fmaf(v[k], v[k], s); }
                v[5] = 1.f; v[6] = -0.5f * L2E * s; v[7] = 0.f;
                float* FH = FhB[nbuf] + tid * 8;
                float* FL = FlB[nbuf] + tid * 8;
                #pragma unroll
                for (int k = 0; k < 8; ++k) {
                    float hi = tf32f(v[k]);
                    FH[k] = hi;
                    FL[k] = tf32f(v[k] - hi);
                }
            }
        }
        __syncthreads();
    }

    // ── reduce j-halves (h=1 -> h=0) via smem, then out = C - U ──
    float4* Sred = (float4*)smem;   // 8 wm x 8 nt x 32 lanes x float4 = 32 KB
    if (h == 1) {
        #pragma unroll
        for (int nt = 0; nt < 8; ++nt)
            Sred[(wm * 8 + nt) * 32 + lane] = make_float4(c[nt][0], c[nt][1],
                                                          c[nt][2], c[nt][3]);
    }
    __syncthreads();
    if (h == 0) {
        const int rl = rbase + g, rh = rl + 8;
        const int n0 = 2 * kin;
        #pragma unroll
        for (int nt = 0; nt < 8; ++nt) {
            float4 v = Sred[(wm * 8 + nt) * 32 + lane];
            const int col = nt * 8 + n0;
            float2 ul = *(const float2*)(U + (size_t)rl * CCH + col);
            float2 uh = *(const float2*)(U + (size_t)rh * CCH + col);
            float2 ol, oh;
            ol.x = (c[nt][0] + v.x) - ul.x; ol.y = (c[nt][1] + v.y) - ul.y;
            oh.x = (c[nt][2] + v.z) - uh.x; oh.y = (c[nt][3] + v.w) - uh.y;
            *(float2*)(out + (size_t)rl * CCH + col) = ol;
            *(float2*)(out + (size_t)rh * CCH + col) = oh;
        }
    }
}

extern "C" void kernel_launch(void* const* d_in, const int* in_sizes, int n_in,
                              void* d_out, int out_size)
{
    const float* U   = (const float*)d_in[0];   // [N, 64]
    const float* ref = (const float*)d_in[1];   // [N, 5]
    float* out = (float*)d_out;                 // [N, 64]
    (void)in_sizes; (void)n_in; (void)out_size;

    cudaFuncSetAttribute(lsh_tmma_kernel,
                         cudaFuncAttributeMaxDynamicSharedMemorySize, SMEM_TOTAL);
    lsh_tmma_kernel<<<N_PTS / BM, TPB, SMEM_TOTAL>>>(U, ref, out);
}

// round 13
// speedup vs baseline: 1.7771x; 1.7771x over previous
#include <cuda_runtime.h>
#include <cstdint>

// LSHGaussian, fp16 mma.sync.m16n8k16 with ldmatrix B-loads:
//   grid=128 CTAs x 512 threads (16 warps = 8 row-blocks x 2 j-halves).
//   U tile stored [j][ch] f16, row stride 144B (bank-disjoint for ldmatrix);
//   B fragments via ldmatrix.m8n8.x4.trans (4 per kc, replaces 16 LDS.32).
//   Scores: scalar packed f32x2 chains (R8 numerics, unchanged).
// out = P @ U - U,  P[i,j] = exp(-0.5*||ref_i-ref_j||^2).

#define N_PTS  16384
#define CCH    64
#define BM     128
#define BK     128
#define TPB    512
#define NTILES (N_PTS / BK)
#define USTRU  36          // u32 per j row (64 f16 = 32 u32 + 4 pad) -> 144B
#define R2STR  12          // u64 per jp row in feature tile

#define US_BYTES (BK * USTRU * 4)      // 18432 per buffer
#define R2_BYTES (64 * R2STR * 8)      // 6144 per buffer
#define OFF_US0  0
#define OFF_US1  US_BYTES
#define OFF_R20  (2 * US_BYTES)
#define OFF_R21  (2 * US_BYTES + R2_BYTES)
#define SMEM_TOTAL (2 * US_BYTES + 2 * R2_BYTES)   // 49152

typedef unsigned long long u64;

__device__ __forceinline__ float ex2f(float x) {
    float r; asm("ex2.approx.ftz.f32 %0, %1;" : "=f"(r) : "f"(x)); return r;
}
__device__ __forceinline__ uint32_t smem_u32(const void* p) {
    uint32_t a;
    asm("{ .reg .u64 t; cvta.to.shared.u64 t, %1; cvt.u32.u64 %0, t; }" : "=r"(a) : "l"(p));
    return a;
}
#define FMA2(acc, a, b) asm("fma.rn.f32x2 %0, %1, %2, %0;" : "+l"(acc) : "l"(a), "l"(b))
#define ADD2(d, a, b)   asm("add.rn.f32x2 %0, %1, %2;" : "=l"(d) : "l"(a), "l"(b))
#define PACKB(d, f)     asm("mov.b64 %0, {%1, %1};" : "=l"(d) : "f"(f))
#define PACK2(d, lo, hi) asm("mov.b64 %0, {%1, %2};" : "=l"(d) : "f"(lo), "f"(hi))
#define UNPK(lo, hi, v) asm("mov.b64 {%0, %1}, %2;" : "=f"(lo), "=f"(hi) : "l"(v))
#define CVTH(d, hi, lo) asm("cvt.rn.f16x2.f32 %0, %1, %2;" : "=r"(d) : "f"(hi), "f"(lo))
#define LDSM4T(r0, r1, r2, r3, addr) \
    asm volatile("ldmatrix.sync.aligned.m8n8.x4.trans.shared.b16 {%0,%1,%2,%3}, [%4];" \
                 : "=r"(r0), "=r"(r1), "=r"(r2), "=r"(r3) : "r"(addr))
#define MMA16(cc, a0, a1, a2, a3, b0, b1) \
    asm volatile("mma.sync.aligned.m16n8k16.row.col.f32.f16.f16.f32 " \
                 "{%0,%1,%2,%3}, {%4,%5,%6,%7}, {%8,%9}, {%0,%1,%2,%3};" \
                 : "+f"((cc)[0]), "+f"((cc)[1]), "+f"((cc)[2]), "+f"((cc)[3]) \
                 : "r"(a0), "r"(a1), "r"(a2), "r"(a3), "r"(b0), "r"(b1))

__global__ void __launch_bounds__(TPB, 1)
lsh_ldsm_kernel(const float* __restrict__ U, const float* __restrict__ ref,
                float* __restrict__ out)
{
    extern __shared__ __align__(16) char smem[];
    uint32_t* const UsB[2] = { (uint32_t*)(smem + OFF_US0), (uint32_t*)(smem + OFF_US1) };
    u64*      const R2B[2] = { (u64*)(smem + OFF_R20), (u64*)(smem + OFF_R21) };
    const uint32_t su = smem_u32(smem);

    const int tid  = threadIdx.x;
    const int wid  = tid >> 5;
    const int lane = tid & 31;
    const int g    = lane >> 2;        // 0..7
    const int kin  = lane & 3;         // 0..3
    const int h    = wid >> 3;         // j-half (0/1)
    const int wm   = wid & 7;          // row-block (16 rows)
    const float L2E = 1.4426950408889634f;
    const int rbase = blockIdx.x * BM + wm * 16;

    // per-lane ldmatrix base: matrix i = lane>>3, row r = lane&7
    const int jpart  = ((lane >> 3) & 1) * 8 + (lane & 7);   // j offset of row
    const int chpart = lane >> 4;                            // ch-chunk offset
    const uint32_t Lbase = (uint32_t)((h * 64 + jpart) * 144 + chpart * 16);

    // 2 A-rows per thread (g, g+8): packed-broadcast ri (scaled) + bias.
    u64 ri2[2][5], bi2[2];
    #pragma unroll
    for (int rr = 0; rr < 2; ++rr) {
        const float* rp = ref + (size_t)(rbase + rr * 8 + g) * 5;
        float s = 0.f;
        #pragma unroll
        for (int k = 0; k < 5; ++k) {
            float v = rp[k];
            s = fmaf(v, v, s);
            PACKB(ri2[rr][k], v * L2E);
        }
        PACKB(bi2[rr], -0.5f * L2E * s);
    }

    float c[8][4];
    #pragma unroll
    for (int nt = 0; nt < 8; ++nt)
        #pragma unroll
        for (int q = 0; q < 4; ++q) c[nt][q] = 0.f;

    // ── stage tile 0 ──
    {
        const float4* Ug = (const float4*)U;
        #pragma unroll
        for (int it = 0; it < 4; ++it) {
            int f = it * TPB + tid;            // 0..2047
            int j = f >> 4, c4 = f & 15;
            float4 v = Ug[f];
            uint2 w;
            CVTH(w.x, v.y, v.x);               // {ch even, ch odd}
            CVTH(w.y, v.w, v.z);
            *(uint2*)&UsB[0][j * USTRU + c4 * 2] = w;
        }
        if (tid < 64) {
            const float* ra = ref + (size_t)(2 * tid) * 5;
            const float* rb = ra + 5;
            float sa = 0.f, sb = 0.f;
            u64* R = &R2B[0][tid * R2STR];
            #pragma unroll
            for (int k = 0; k < 5; ++k) {
                float a = ra[k], b = rb[k];
                sa = fmaf(a, a, sa); sb = fmaf(b, b, sb);
                PACK2(R[k], a, b);
            }
            PACK2(R[5], -0.5f * L2E * sa, -0.5f * L2E * sb);
        }
    }
    __syncthreads();

    for (int t = 0; t < NTILES; ++t) {
        const int buf = t & 1, nbuf = buf ^ 1;
        const bool pfv = (t + 1 < NTILES);

        // prefetch next tile into registers
        float4 pf[4]; float pa[5], pb[5];
        if (pfv) {
            const float4* Ug = (const float4*)(U + (size_t)(t + 1) * BK * CCH);
            #pragma unroll
            for (int it = 0; it < 4; ++it) pf[it] = Ug[it * TPB + tid];
            if (tid < 64) {
                const float* ra = ref + (size_t)((t + 1) * BK + 2 * tid) * 5;
                #pragma unroll
                for (int k = 0; k < 5; ++k) { pa[k] = ra[k]; pb[k] = ra[k + 5]; }
            }
        }

        // ── compute tile t: 4 k-chunks of 16 j ──
        {
            const u64* __restrict__ R2 = R2B[buf];
            const uint32_t Ls = su + (buf ? OFF_US1 : OFF_US0) + Lbase;
            #pragma unroll
            for (int kc = 0; kc < 4; ++kc) {
                const int jpA = h * 32 + kc * 8 + kin;   // feature row (j-pair)
                const int jpB = jpA + 4;
                const u64* Ra = &R2[jpA * R2STR];
                const u64* Rb = &R2[jpB * R2STR];
                ulonglong2 xa01 = *(const ulonglong2*)&Ra[0];
                ulonglong2 xa23 = *(const ulonglong2*)&Ra[2];
                ulonglong2 xa45 = *(const ulonglong2*)&Ra[4];
                ulonglong2 xb01 = *(const ulonglong2*)&Rb[0];
                ulonglong2 xb23 = *(const ulonglong2*)&Rb[2];
                ulonglong2 xb45 = *(const ulonglong2*)&Rb[4];

                u64 tA0, tA1, tB0, tB1;
                ADD2(tA0, xa45.y, bi2[0]); ADD2(tA1, xa45.y, bi2[1]);
                ADD2(tB0, xb45.y, bi2[0]); ADD2(tB1, xb45.y, bi2[1]);
                FMA2(tA0, ri2[0][0], xa01.x); FMA2(tA1, ri2[1][0], xa01.x);
                FMA2(tB0, ri2[0][0], xb01.x); FMA2(tB1, ri2[1][0], xb01.x);
                FMA2(tA0, ri2[0][1], xa01.y); FMA2(tA1, ri2[1][1], xa01.y);
                FMA2(tB0, ri2[0][1], xb01.y); FMA2(tB1, ri2[1][1], xb01.y);
                FMA2(tA0, ri2[0][2], xa23.x); FMA2(tA1, ri2[1][2], xa23.x);
                FMA2(tB0, ri2[0][2], xb23.x); FMA2(tB1, ri2[1][2], xb23.x);
                FMA2(tA0, ri2[0][3], xa23.y); FMA2(tA1, ri2[1][3], xa23.y);
                FMA2(tB0, ri2[0][3], xb23.y); FMA2(tB1, ri2[1][3], xb23.y);
                FMA2(tA0, ri2[0][4], xa45.x); FMA2(tA1, ri2[1][4], xa45.x);
                FMA2(tB0, ri2[0][4], xb45.x); FMA2(tB1, ri2[1][4], xb45.x);

                float e, o;
                uint32_t a0, a1, a2, a3;
                UNPK(e, o, tA0); e = ex2f(e); o = ex2f(o); CVTH(a0, o, e);
                UNPK(e, o, tA1); e = ex2f(e); o = ex2f(o); CVTH(a1, o, e);
                UNPK(e, o, tB0); e = ex2f(e); o = ex2f(o); CVTH(a2, o, e);
                UNPK(e, o, tB1); e = ex2f(e); o = ex2f(o); CVTH(a3, o, e);

                // B fragments via ldmatrix.x4.trans: each call covers 2 n-tiles.
                const uint32_t ad = Ls + (uint32_t)(kc * 16 * 144);
                #pragma unroll
                for (int q = 0; q < 4; ++q) {
                    uint32_t b00, b01, b10, b11;
                    LDSM4T(b00, b01, b10, b11, ad + (uint32_t)(q * 32));
                    MMA16(c[2 * q],     a0, a1, a2, a3, b00, b01);
                    MMA16(c[2 * q + 1], a0, a1, a2, a3, b10, b11);
                }
            }
        }

        // ── stage tile t+1 ──
        if (pfv) {
            uint32_t* Ud = UsB[nbuf];
            #pragma unroll
            for (int it = 0; it < 4; ++it) {
                int f = it * TPB + tid, j = f >> 4, c4 = f & 15;
                uint2 w;
                CVTH(w.x, pf[it].y, pf[it].x);
                CVTH(w.y, pf[it].w, pf[it].z);
                *(uint2*)&Ud[j * USTRU + c4 * 2] = w;
            }
            if (tid < 64) {
                float sa = 0.f, sb = 0.f;
                u64* R = &R2B[nbuf][tid * R2STR];
                #pragma unroll
                for (int k = 0; k < 5; ++k) {
                    sa = fmaf(pa[k], pa[k], sa); sb = fmaf(pb[k], pb[k], sb);
                    PACK2(R[k], pa[k], pb[k]);
                }
                PACK2(R[5], -0.5f * L2E * sa, -0.5f * L2E * sb);
            }
        }
        __syncthreads();
    }

    // ── reduce j-halves (h=1 -> h=0) via smem, then out = C - U ──
    float4* Sred = (float4*)smem;   // 8 wm x 8 nt x 32 lanes x float4 = 32 KB
    if (h == 1) {
        #pragma unroll
        for (int nt = 0; nt < 8; ++nt)
            Sred[(wm * 8 + nt) * 32 + lane] = make_float4(c[nt][0], c[nt][1],
                                                          c[nt][2], c[nt][3]);
    }
    __syncthreads();
    if (h == 0) {
        const int rl = rbase + g, rh = rl + 8;
        const int n0 = 2 * kin;
        #pragma unroll
        for (int nt = 0; nt < 8; ++nt) {
            float4 v = Sred[(wm * 8 + nt) * 32 + lane];
            const int col = nt * 8 + n0;
            float2 ul = *(const float2*)(U + (size_t)rl * CCH + col);
            float2 uh = *(const float2*)(U + (size_t)rh * CCH + col);
            float2 ol, oh;
            ol.x = (c[nt][0] + v.x) - ul.x; ol.y = (c[nt][1] + v.y) - ul.y;
            oh.x = (c[nt][2] + v.z) - uh.x; oh.y = (c[nt][3] + v.w) - uh.y;
            *(float2*)(out + (size_t)rl * CCH + col) = ol;
            *(float2*)(out + (size_t)rh * CCH + col) = oh;
        }
    }
}

extern "C" void kernel_launch(void* const* d_in, const int* in_sizes, int n_in,
                              void* d_out, int out_size)
{
    const float* U   = (const float*)d_in[0];   // [N, 64]
    const float* ref = (const float*)d_in[1];   // [N, 5]
    float* out = (float*)d_out;                 // [N, 64]
    (void)in_sizes; (void)n_in; (void)out_size;

    cudaFuncSetAttribute(lsh_ldsm_kernel,
                         cudaFuncAttributeMaxDynamicSharedMemorySize, SMEM_TOTAL);
    lsh_ldsm_kernel<<<N_PTS / BM, TPB, SMEM_TOTAL>>>(U, ref, out);
}